// round 15
// baseline (speedup 1.0000x reference)
#include <cuda_runtime.h>
#include <math.h>

#define BATCH 8
#define IMH 512
#define IMW 512
#define NP 11
#define NMAPS (BATCH * NP)

// packed derived parameters (pair-interleaved conv weights for FFMA2)
// [0,588)    sw2  : 49 taps x 6 channel-pairs x 2  (slot = tap*12 + k, k<11;
//                   slot tap*12+11 is a zero hole)
// [588,600)  sb2  : 6 bias pairs (slot 588+k, k<11; 599 = zero hole)
// [600,894)  cw   : 3 cascades x 2 dims x 49 taps
// [894,900)  cb   : 3 cascades x 2 dims
#define OFF_SW2   0
#define OFF_SB2   588
#define OFF_CW    600
#define OFF_CB    894
#define NPARAMS   900

#define TSTRIDE 144            // tile row stride (floats), 16B-aligned rows
#define SPOS    561            // 17 x 33 score positions per tile

__device__ __align__(16) float g_params_dev[NPARAMS];

__device__ unsigned long long g_best[NMAPS];
__device__ unsigned int       g_count[BATCH];

// ---------------------------------------------------------------------------
// Kernel 1: fold weights — one warp per output o in [0,850). Warp 850 zeros
// the pair-layout holes. Block 0 resets the argmax combine state.
// ---------------------------------------------------------------------------
__global__ void prep_kernel(const float* __restrict__ bw,
                            const float* __restrict__ bb,
                            const float* __restrict__ fcw,
                            const float* __restrict__ fcb,
                            const float* __restrict__ hw,
                            const float* __restrict__ hb) {
    const int o = (blockIdx.x * blockDim.x + threadIdx.x) >> 5;
    const int l = threadIdx.x & 31;

    if (blockIdx.x == 0) {
        if (threadIdx.x < NMAPS) g_best[threadIdx.x] = 0ULL;
        if (threadIdx.x < BATCH) g_count[threadIdx.x] = 0u;
    }
    if (o > 850) return;

    if (o == 850) {                           // zero holes in pair layout
        if (l < 49) g_params_dev[OFF_SW2 + l * 12 + 11] = 0.f;
        int l2 = l + 32;
        if (l2 < 49) g_params_dev[OFF_SW2 + l2 * 12 + 11] = 0.f;
        if (l == 0)  g_params_dev[OFF_SB2 + 11] = 0.f;
        return;
    }

    float acc = 0.f;
    if (o < 833) {
        const int grp = o / 49, p = o - grp * 49;   // warp-uniform
        if (grp < 11) {
            #pragma unroll
            for (int s = 0; s < 8; ++s) {
                int c = l + 32 * s;
                const float* base = bw + c * 147 + p;
                float we = base[0] + base[49] + base[98];
                acc += fcw[grp * 256 + c] * we;
            }
        } else {
            const int ij = grp - 11, i = ij >> 1, j = ij & 1;
            #pragma unroll
            for (int s = 0; s < 8; ++s) {
                int c = l + 32 * s;
                const float* base = bw + c * 147 + p;
                float we = base[0] + base[49] + base[98];
                acc += hw[(i * 256 + c) * 2 + j] * we;
            }
        }
    } else if (o < 844) {
        const int k = o - 833;
        #pragma unroll
        for (int s = 0; s < 8; ++s) {
            int c = l + 32 * s;
            acc += fcw[k * 256 + c] * bb[c];
        }
    } else {
        const int ij = o - 844, i = ij >> 1, j = ij & 1;
        #pragma unroll
        for (int s = 0; s < 8; ++s) {
            int c = l + 32 * s;
            acc += hw[(i * 256 + c) * 2 + j] * bb[c];
        }
    }

    #pragma unroll
    for (int sft = 16; sft; sft >>= 1)
        acc += __shfl_down_sync(0xffffffffu, acc, sft);

    if (l == 0) {
        int slot; float base = 0.f;
        if (o < 539) {
            const int grp = o / 49, p = o - grp * 49;
            slot = OFF_SW2 + p * 12 + grp;          // pair-interleaved
        } else if (o < 833) {
            slot = OFF_CW + (o - 539);
        } else if (o < 844) {
            slot = OFF_SB2 + (o - 833); base = fcb[o - 833];
        } else {
            slot = OFF_CB + (o - 844);  base = hb[o - 844];
        }
        g_params_dev[slot] = base + acc;
    }
}

// ---------------------------------------------------------------------------
// Kernel 2 (fused): 256 blocks of 16x32-cell tiles, 352 threads (11 warps).
// PDL: prologue (cp.async raw tile + endpoint table) needs only img; then
// cudaGridDependencySynchronize() before reading prep's params. Normalization
// folded into biases (b' = b - 0.5*sum(w)); pad = raw 0.5. Conv: FFMA2,
// 2 pos/thread, aligned LDS.128 value+weight loads. Then smem scores ->
// cell-corner argmax scan -> per-map atomicMax -> last block per batch:
// cascades (cw/cb from smem; shift = p - 0.5*sum(cw) + cb).
// ---------------------------------------------------------------------------
__global__ void conv_scan_kernel(const float* __restrict__ img,
                                 float* __restrict__ out) {
    __shared__ __align__(16) float sbuf[74 * TSTRIDE]; // raw tile, then scores
    __shared__ __align__(16) float wsm[NPARAMS];
    __shared__ float4 tab[128];
    __shared__ unsigned int s_ticket;

    const int tx = blockIdx.x;                 // 0..3
    const int ty = blockIdx.y;                 // 0..7
    const int b  = blockIdx.z;                 // 0..7
    const int tid  = threadIdx.x;              // 0..351
    const int lane = tid & 31;
    const int wid  = tid >> 5;                 // 0..10
    const int gy0 = ty * 16, gx0 = tx * 32;
    const float STEP = 127.0f / 511.0f;

    const float* imb = img + (size_t)b * IMH * IMW;
    const int ir0 = ty * 64 - 3;
    const int icA = tx * 128 - 4;              // aligned tile base column

    // phase 0a (pre-dependency): raw tile via cp.async + endpoint table
    {
        const unsigned int sbase =
            (unsigned int)__cvta_generic_to_shared(sbuf);
        for (int i = tid; i < 74 * 36; i += 352) {
            const int r = i / 36, j4 = i - r * 36;
            const int gr = ir0 + r;
            const int gc = icA + j4 * 4;
            float* dst = sbuf + r * TSTRIDE + j4 * 4;
            if (gr >= 0 && gr < IMH && gc >= 0 && gc <= IMW - 4) {
                const float* gp = imb + gr * IMW + gc;
                unsigned int sa = sbase + (unsigned int)((r * TSTRIDE + j4 * 4) * 4);
                asm volatile("cp.async.ca.shared.global [%0], [%1], 16;"
                             :: "r"(sa), "l"(gp) : "memory");
            } else if (gr >= 0 && gr < IMH) {
                float4 q;
                q.x = (gc + 0 >= 0 && gc + 0 < IMW) ? imb[gr * IMW + gc + 0] : 0.5f;
                q.y = (gc + 1 >= 0 && gc + 1 < IMW) ? imb[gr * IMW + gc + 1] : 0.5f;
                q.z = (gc + 2 >= 0 && gc + 2 < IMW) ? imb[gr * IMW + gc + 2] : 0.5f;
                q.w = (gc + 3 >= 0 && gc + 3 < IMW) ? imb[gr * IMW + gc + 3] : 0.5f;
                *reinterpret_cast<float4*>(dst) = q;
            } else {
                *reinterpret_cast<float4*>(dst) = make_float4(0.5f, 0.5f, 0.5f, 0.5f);
            }
        }
        asm volatile("cp.async.commit_group;" ::: "memory");
    }

    for (int oy = tid; oy < 512; oy += 352) {
        float ys = (float)oy * STEP;
        int y0 = (int)ys;
        float wy = ys - (float)y0;
        int y0m = (oy > 0)   ? (int)((float)(oy - 1) * STEP) : -1;
        int y0p = (oy < 511) ? (int)((float)(oy + 1) * STEP) : 128;
        if (y0m != y0) { tab[y0].x = wy; tab[y0].z = __int_as_float(oy); }
        if (y0p != y0) { tab[y0].y = wy; tab[y0].w = __int_as_float(oy); }
    }

    // wait for prep's params (PDL; trivially satisfied on serialized launch)
    cudaGridDependencySynchronize();

    // phase 0b: params -> smem
    for (int i = tid; i < NPARAMS; i += 352) wsm[i] = g_params_dev[i];

    asm volatile("cp.async.wait_group 0;" ::: "memory");
    __syncthreads();

    // phase 0c: fold -0.5*sum(w) into biases (per map; warp w -> map w)
    {
        float s1 = (lane < 49) ? wsm[lane * 12 + wid] : 0.f;
        const int p2 = lane + 32;
        if (p2 < 49) s1 += wsm[p2 * 12 + wid];
        #pragma unroll
        for (int sft = 16; sft; sft >>= 1)
            s1 += __shfl_down_sync(0xffffffffu, s1, sft);
        if (lane == 0) wsm[OFF_SB2 + wid] -= 0.5f * s1;
    }
    __syncthreads();

    // phase 1: conv — positions pos0=tid, pos1=min(tid+352,560)
    const int pos0 = tid;
    const int pos1 = min(tid + 352, 560);
    const int r0 = pos0 / 33, c0 = pos0 - r0 * 33;
    const int r1 = pos1 / 33, c1 = pos1 - r1 * 33;
    const float* tp0 = sbuf + (r0 * 4) * TSTRIDE + c0 * 4;
    const float* tp1 = sbuf + (r1 * 4) * TSTRIDE + c1 * 4;

    unsigned long long acc2[2][6];
    {
        const ulonglong2 b01 =
            *reinterpret_cast<const ulonglong2*>(&wsm[OFF_SB2]);
        const ulonglong2 b23 =
            *reinterpret_cast<const ulonglong2*>(&wsm[OFF_SB2 + 4]);
        const ulonglong2 b45 =
            *reinterpret_cast<const ulonglong2*>(&wsm[OFF_SB2 + 8]);
        acc2[0][0] = b01.x; acc2[0][1] = b01.y;
        acc2[0][2] = b23.x; acc2[0][3] = b23.y;
        acc2[0][4] = b45.x; acc2[0][5] = b45.y;
        #pragma unroll
        for (int j = 0; j < 6; ++j) acc2[1][j] = acc2[0][j];
    }

    #pragma unroll
    for (int kh = 0; kh < 7; ++kh) {
        const float* rp0 = tp0 + kh * TSTRIDE;
        const float* rp1 = tp1 + kh * TSTRIDE;
        float4 Qa0 = *reinterpret_cast<const float4*>(rp0);
        float4 Qb0 = *reinterpret_cast<const float4*>(rp0 + 4);
        float4 Qa1 = *reinterpret_cast<const float4*>(rp1);
        float4 Qb1 = *reinterpret_cast<const float4*>(rp1 + 4);
        float v0[7] = {Qa0.y, Qa0.z, Qa0.w, Qb0.x, Qb0.y, Qb0.z, Qb0.w};
        float v1[7] = {Qa1.y, Qa1.z, Qa1.w, Qb1.x, Qb1.y, Qb1.z, Qb1.w};
        #pragma unroll
        for (int kw = 0; kw < 7; ++kw) {
            const int tapo = (kh * 7 + kw) * 12;
            unsigned long long vv0, vv1;
            asm("mov.b64 %0, {%1, %1};" : "=l"(vv0) : "f"(v0[kw]));
            asm("mov.b64 %0, {%1, %1};" : "=l"(vv1) : "f"(v1[kw]));
            const ulonglong2 w01 =
                *reinterpret_cast<const ulonglong2*>(&wsm[OFF_SW2 + tapo]);
            const ulonglong2 w23 =
                *reinterpret_cast<const ulonglong2*>(&wsm[OFF_SW2 + tapo + 4]);
            const ulonglong2 w45 =
                *reinterpret_cast<const ulonglong2*>(&wsm[OFF_SW2 + tapo + 8]);
            asm("fma.rn.f32x2 %0, %1, %2, %3;"
                : "=l"(acc2[0][0]) : "l"(w01.x), "l"(vv0), "l"(acc2[0][0]));
            asm("fma.rn.f32x2 %0, %1, %2, %3;"
                : "=l"(acc2[1][0]) : "l"(w01.x), "l"(vv1), "l"(acc2[1][0]));
            asm("fma.rn.f32x2 %0, %1, %2, %3;"
                : "=l"(acc2[0][1]) : "l"(w01.y), "l"(vv0), "l"(acc2[0][1]));
            asm("fma.rn.f32x2 %0, %1, %2, %3;"
                : "=l"(acc2[1][1]) : "l"(w01.y), "l"(vv1), "l"(acc2[1][1]));
            asm("fma.rn.f32x2 %0, %1, %2, %3;"
                : "=l"(acc2[0][2]) : "l"(w23.x), "l"(vv0), "l"(acc2[0][2]));
            asm("fma.rn.f32x2 %0, %1, %2, %3;"
                : "=l"(acc2[1][2]) : "l"(w23.x), "l"(vv1), "l"(acc2[1][2]));
            asm("fma.rn.f32x2 %0, %1, %2, %3;"
                : "=l"(acc2[0][3]) : "l"(w23.y), "l"(vv0), "l"(acc2[0][3]));
            asm("fma.rn.f32x2 %0, %1, %2, %3;"
                : "=l"(acc2[1][3]) : "l"(w23.y), "l"(vv1), "l"(acc2[1][3]));
            asm("fma.rn.f32x2 %0, %1, %2, %3;"
                : "=l"(acc2[0][4]) : "l"(w45.x), "l"(vv0), "l"(acc2[0][4]));
            asm("fma.rn.f32x2 %0, %1, %2, %3;"
                : "=l"(acc2[1][4]) : "l"(w45.x), "l"(vv1), "l"(acc2[1][4]));
            asm("fma.rn.f32x2 %0, %1, %2, %3;"
                : "=l"(acc2[0][5]) : "l"(w45.y), "l"(vv0), "l"(acc2[0][5]));
            asm("fma.rn.f32x2 %0, %1, %2, %3;"
                : "=l"(acc2[1][5]) : "l"(w45.y), "l"(vv1), "l"(acc2[1][5]));
        }
    }
    __syncthreads();                            // all tile reads done

    // phase 2: overlay scores into sbuf: s[k*561 + pos]
    #pragma unroll
    for (int j = 0; j < 6; ++j) {
        unsigned int lo0 = (unsigned int)(acc2[0][j] & 0xFFFFFFFFull);
        sbuf[(2 * j) * 561 + pos0] = __uint_as_float(lo0);
        if (j < 5) {
            unsigned int hi0 = (unsigned int)(acc2[0][j] >> 32);
            sbuf[(2 * j + 1) * 561 + pos0] = __uint_as_float(hi0);
        }
    }
    if (tid < 209) {
        #pragma unroll
        for (int j = 0; j < 6; ++j) {
            unsigned int lo1 = (unsigned int)(acc2[1][j] & 0xFFFFFFFFull);
            sbuf[(2 * j) * 561 + pos1] = __uint_as_float(lo1);
            if (j < 5) {
                unsigned int hi1 = (unsigned int)(acc2[1][j] >> 32);
                sbuf[(2 * j + 1) * 561 + pos1] = __uint_as_float(hi1);
            }
        }
    }
    __syncthreads();

    // phase 3: scan — warp wid handles map k = wid; lane = cell column
    {
        const int k = wid;
        const int gx = gx0 + lane;
        const int c1l = min(gx + 1, 127) - gx0;
        const float* s = sbuf + k * 561;
        const float4 tx4 = tab[gx];

        float a  = s[lane];
        float bq = s[c1l];
        float best = -3.0e38f;
        int bidx = 0x7fffffff;

        #pragma unroll 4
        for (int r = 0; r < 16; ++r) {
            const int gy = gy0 + r;
            const int y1l = min(gy + 1, 127) - gy0;
            const float cc = s[y1l * 33 + lane];
            const float dd = s[y1l * 33 + c1l];
            const float4 ty4 = tab[gy];
            const float ca = cc - a, db = dd - bq;
            {   // y-lo endpoint row
                float rl = fmaf(ty4.x, ca, a);
                float rr = fmaf(ty4.x, db, bq);
                float dx = rr - rl;
                bool hx = dx > 0.f;
                float w  = hx ? tx4.y : tx4.x;
                int  oxs = __float_as_int(hx ? tx4.w : tx4.z);
                float v = fmaf(w, dx, rl);
                int idx = (__float_as_int(ty4.z) << 9) + oxs;
                if (v > best) { best = v; bidx = idx; }
            }
            {   // y-hi endpoint row
                float rl = fmaf(ty4.y, ca, a);
                float rr = fmaf(ty4.y, db, bq);
                float dx = rr - rl;
                bool hx = dx > 0.f;
                float w  = hx ? tx4.y : tx4.x;
                int  oxs = __float_as_int(hx ? tx4.w : tx4.z);
                float v = fmaf(w, dx, rl);
                int idx = (__float_as_int(ty4.w) << 9) + oxs;
                if (v > best) { best = v; bidx = idx; }
            }
            a = cc; bq = dd;
        }

        #pragma unroll
        for (int sft = 16; sft; sft >>= 1) {
            float v2 = __shfl_down_sync(0xffffffffu, best, sft);
            int   i2 = __shfl_down_sync(0xffffffffu, bidx, sft);
            if (v2 > best || (v2 == best && i2 < bidx)) { best = v2; bidx = i2; }
        }
        if (lane == 0) {
            unsigned int u = __float_as_uint(best);
            u = (u & 0x80000000u) ? ~u : (u | 0x80000000u);
            unsigned long long key =
                ((unsigned long long)u << 32) | (0xFFFFFFFFu - (unsigned int)bidx);
            atomicMax(&g_best[b * NP + k], key);
        }
    }

    __syncthreads();
    if (tid == 0) {
        __threadfence();
        s_ticket = atomicAdd(&g_count[b], 1u);
    }
    __syncthreads();

    // phase 4: last block of this batch: cascades, warp k -> point k
    // (raw gather, pad 0.5; shift = p - 0.5*sum(cw) + cb; cw/cb from smem)
    if (s_ticket == 31u) {
        __threadfence();
        const int k = wid;
        unsigned long long key = 0ULL;
        if (lane == 0) key = atomicAdd(&g_best[b * NP + k], 0ULL);
        unsigned int lo =
            __shfl_sync(0xffffffffu, (unsigned int)(key & 0xFFFFFFFFull), 0);
        int idx = (int)(0xFFFFFFFFu - lo);
        float cx = (float)(idx & 511);
        float cy = (float)(idx >> 9);

        for (int casc = 0; casc < 3; ++casc) {
            int wi = (int)rintf(cx * 0.25f); wi = max(0, min(wi, 127));
            int hi = (int)rintf(cy * 0.25f); hi = max(0, min(hi, 127));
            float p0 = 0.f, p1 = 0.f, w0 = 0.f, w1 = 0.f;
            for (int t = lane; t < 49; t += 32) {
                int kh = t / 7, kw = t - kh * 7;
                int iy = hi * 4 - 3 + kh;
                int ix = wi * 4 - 3 + kw;
                float v = 0.5f;
                if (iy >= 0 && iy < IMH && ix >= 0 && ix < IMW)
                    v = imb[iy * IMW + ix];
                float c0v = wsm[OFF_CW + (casc * 2 + 0) * 49 + t];
                float c1v = wsm[OFF_CW + (casc * 2 + 1) * 49 + t];
                p0 += v * c0v;  w0 += c0v;
                p1 += v * c1v;  w1 += c1v;
            }
            #pragma unroll
            for (int sft = 16; sft; sft >>= 1) {
                p0 += __shfl_down_sync(0xffffffffu, p0, sft);
                p1 += __shfl_down_sync(0xffffffffu, p1, sft);
                w0 += __shfl_down_sync(0xffffffffu, w0, sft);
                w1 += __shfl_down_sync(0xffffffffu, w1, sft);
            }
            p0 = __shfl_sync(0xffffffffu, p0, 0);
            p1 = __shfl_sync(0xffffffffu, p1, 0);
            w0 = __shfl_sync(0xffffffffu, w0, 0);
            w1 = __shfl_sync(0xffffffffu, w1, 0);
            cx = cx + (p0 - 0.5f * w0) + wsm[OFF_CB + casc * 2 + 0];
            cy = cy + (p1 - 0.5f * w1) + wsm[OFF_CB + casc * 2 + 1];
        }
        if (lane == 0) {
            out[(b * NP + k) * 2 + 0] = cx;
            out[(b * NP + k) * 2 + 1] = cy;
        }
    }
}

// ---------------------------------------------------------------------------
extern "C" void kernel_launch(void* const* d_in, const int* in_sizes, int n_in,
                              void* d_out, int out_size) {
    const float* img = (const float*)d_in[0];
    const float* bw  = (const float*)d_in[1];
    const float* bb  = (const float*)d_in[2];
    const float* fcw = (const float*)d_in[3];
    const float* fcb = (const float*)d_in[4];
    const float* hw  = (const float*)d_in[5];
    const float* hb  = (const float*)d_in[6];
    float* out = (float*)d_out;

    prep_kernel<<<107, 256>>>(bw, bb, fcw, fcb, hw, hb);

    dim3 g(4, 8, BATCH);

    // PDL launch: conv_scan prologue (tile cp.async + table) overlaps prep;
    // cudaGridDependencySynchronize() gates the params read. Fallback to a
    // plain launch (gridDepSync is trivially satisfied when serialized).
    cudaLaunchConfig_t cfg = {};
    cfg.gridDim = g;
    cfg.blockDim = dim3(352, 1, 1);
    cfg.dynamicSmemBytes = 0;
    cfg.stream = 0;
    cudaLaunchAttribute attr[1];
    attr[0].id = cudaLaunchAttributeProgrammaticStreamSerialization;
    attr[0].val.programmaticStreamSerializationAllowed = 1;
    cfg.attrs = attr;
    cfg.numAttrs = 1;

    cudaError_t err = cudaLaunchKernelEx(&cfg, conv_scan_kernel, img, out);
    if (err != cudaSuccess) {
        conv_scan_kernel<<<g, 352>>>(img, out);
    }
}

// round 16
// speedup vs baseline: 1.4781x; 1.4781x over previous
#include <cuda_runtime.h>
#include <math.h>

#define BATCH 8
#define IMH 512
#define IMW 512
#define NP 11
#define NMAPS (BATCH * NP)

// packed derived parameters (pair-interleaved conv weights for FFMA2)
// [0,588)    sw2  : 49 taps x 6 channel-pairs x 2  (slot = tap*12 + k, k<11;
//                   slot tap*12+11 is a zero hole)
// [588,600)  sb2  : 6 bias pairs (slot 588+k, k<11; 599 = zero hole)
// [600,894)  cw   : 3 cascades x 2 dims x 49 taps
// [894,900)  cb   : 3 cascades x 2 dims
#define OFF_SW2   0
#define OFF_SB2   588
#define OFF_CW    600
#define OFF_CB    894
#define NPARAMS   900

#define TSTRIDE 144            // tile row stride (floats), 16B-aligned rows
#define SPOS    561            // 17 x 33 score positions per tile

__device__ __align__(16) float g_params_dev[NPARAMS];

__device__ unsigned long long g_best[NMAPS];
__device__ unsigned int       g_count[BATCH];

// ---------------------------------------------------------------------------
// Kernel 1: fold weights — one warp per output o in [0,850). Warp 850 zeros
// the pair-layout holes. Block 0 resets the argmax combine state.
// ---------------------------------------------------------------------------
__global__ void prep_kernel(const float* __restrict__ bw,
                            const float* __restrict__ bb,
                            const float* __restrict__ fcw,
                            const float* __restrict__ fcb,
                            const float* __restrict__ hw,
                            const float* __restrict__ hb) {
    const int o = (blockIdx.x * blockDim.x + threadIdx.x) >> 5;
    const int l = threadIdx.x & 31;

    if (blockIdx.x == 0) {
        if (threadIdx.x < NMAPS) g_best[threadIdx.x] = 0ULL;
        if (threadIdx.x < BATCH) g_count[threadIdx.x] = 0u;
    }
    if (o > 850) return;

    if (o == 850) {                           // zero holes in pair layout
        if (l < 49) g_params_dev[OFF_SW2 + l * 12 + 11] = 0.f;
        int l2 = l + 32;
        if (l2 < 49) g_params_dev[OFF_SW2 + l2 * 12 + 11] = 0.f;
        if (l == 0)  g_params_dev[OFF_SB2 + 11] = 0.f;
        return;
    }

    float acc = 0.f;
    if (o < 833) {
        const int grp = o / 49, p = o - grp * 49;   // warp-uniform
        if (grp < 11) {
            #pragma unroll
            for (int s = 0; s < 8; ++s) {
                int c = l + 32 * s;
                const float* base = bw + c * 147 + p;
                float we = base[0] + base[49] + base[98];
                acc += fcw[grp * 256 + c] * we;
            }
        } else {
            const int ij = grp - 11, i = ij >> 1, j = ij & 1;
            #pragma unroll
            for (int s = 0; s < 8; ++s) {
                int c = l + 32 * s;
                const float* base = bw + c * 147 + p;
                float we = base[0] + base[49] + base[98];
                acc += hw[(i * 256 + c) * 2 + j] * we;
            }
        }
    } else if (o < 844) {
        const int k = o - 833;
        #pragma unroll
        for (int s = 0; s < 8; ++s) {
            int c = l + 32 * s;
            acc += fcw[k * 256 + c] * bb[c];
        }
    } else {
        const int ij = o - 844, i = ij >> 1, j = ij & 1;
        #pragma unroll
        for (int s = 0; s < 8; ++s) {
            int c = l + 32 * s;
            acc += hw[(i * 256 + c) * 2 + j] * bb[c];
        }
    }

    #pragma unroll
    for (int sft = 16; sft; sft >>= 1)
        acc += __shfl_down_sync(0xffffffffu, acc, sft);

    if (l == 0) {
        int slot; float base = 0.f;
        if (o < 539) {
            const int grp = o / 49, p = o - grp * 49;
            slot = OFF_SW2 + p * 12 + grp;          // pair-interleaved
        } else if (o < 833) {
            slot = OFF_CW + (o - 539);
        } else if (o < 844) {
            slot = OFF_SB2 + (o - 833); base = fcb[o - 833];
        } else {
            slot = OFF_CB + (o - 844);  base = hb[o - 844];
        }
        g_params_dev[slot] = base + acc;
    }
}

// ---------------------------------------------------------------------------
// Kernel 2 (fused): 256 blocks of 16x32-cell tiles, 352 threads (11 warps).
// Raw-image tile AND params staged via cp.async (one commit group, one
// wait). Normalization folded into biases (b' = b - 0.5*sum(w)); pad = raw
// 0.5. Conv: FFMA2, 2 pos/thread, aligned LDS.128 value+weight loads. Then
// smem scores -> cell-corner argmax scan -> per-map atomicMax -> last block
// per batch: cascades (cw/cb from smem; shift = p - 0.5*sum(cw) + cb).
// ---------------------------------------------------------------------------
__global__ void conv_scan_kernel(const float* __restrict__ img,
                                 float* __restrict__ out) {
    __shared__ __align__(16) float sbuf[74 * TSTRIDE]; // raw tile, then scores
    __shared__ __align__(16) float wsm[NPARAMS];
    __shared__ float4 tab[128];
    __shared__ unsigned int s_ticket;

    const int tx = blockIdx.x;                 // 0..3
    const int ty = blockIdx.y;                 // 0..7
    const int b  = blockIdx.z;                 // 0..7
    const int tid  = threadIdx.x;              // 0..351
    const int lane = tid & 31;
    const int wid  = tid >> 5;                 // 0..10
    const int gy0 = ty * 16, gx0 = tx * 32;
    const float STEP = 127.0f / 511.0f;

    const float* imb = img + (size_t)b * IMH * IMW;
    const int ir0 = ty * 64 - 3;
    const int icA = tx * 128 - 4;              // aligned tile base column

    // phase 0: params + raw tile via cp.async (single group), endpoint table
    {
        if (tid < NPARAMS / 4) {               // 225 float4 copies
            unsigned int sa =
                (unsigned int)__cvta_generic_to_shared(wsm) + tid * 16u;
            const float* gp = g_params_dev + tid * 4;
            asm volatile("cp.async.ca.shared.global [%0], [%1], 16;"
                         :: "r"(sa), "l"(gp) : "memory");
        }

        const unsigned int sbase =
            (unsigned int)__cvta_generic_to_shared(sbuf);
        for (int i = tid; i < 74 * 36; i += 352) {
            const int r = i / 36, j4 = i - r * 36;
            const int gr = ir0 + r;
            const int gc = icA + j4 * 4;
            float* dst = sbuf + r * TSTRIDE + j4 * 4;
            if (gr >= 0 && gr < IMH && gc >= 0 && gc <= IMW - 4) {
                const float* gp = imb + gr * IMW + gc;
                unsigned int sa = sbase + (unsigned int)((r * TSTRIDE + j4 * 4) * 4);
                asm volatile("cp.async.ca.shared.global [%0], [%1], 16;"
                             :: "r"(sa), "l"(gp) : "memory");
            } else if (gr >= 0 && gr < IMH) {
                float4 q;
                q.x = (gc + 0 >= 0 && gc + 0 < IMW) ? imb[gr * IMW + gc + 0] : 0.5f;
                q.y = (gc + 1 >= 0 && gc + 1 < IMW) ? imb[gr * IMW + gc + 1] : 0.5f;
                q.z = (gc + 2 >= 0 && gc + 2 < IMW) ? imb[gr * IMW + gc + 2] : 0.5f;
                q.w = (gc + 3 >= 0 && gc + 3 < IMW) ? imb[gr * IMW + gc + 3] : 0.5f;
                *reinterpret_cast<float4*>(dst) = q;
            } else {
                *reinterpret_cast<float4*>(dst) = make_float4(0.5f, 0.5f, 0.5f, 0.5f);
            }
        }
        asm volatile("cp.async.commit_group;" ::: "memory");
    }

    for (int oy = tid; oy < 512; oy += 352) {
        float ys = (float)oy * STEP;
        int y0 = (int)ys;
        float wy = ys - (float)y0;
        int y0m = (oy > 0)   ? (int)((float)(oy - 1) * STEP) : -1;
        int y0p = (oy < 511) ? (int)((float)(oy + 1) * STEP) : 128;
        if (y0m != y0) { tab[y0].x = wy; tab[y0].z = __int_as_float(oy); }
        if (y0p != y0) { tab[y0].y = wy; tab[y0].w = __int_as_float(oy); }
    }

    asm volatile("cp.async.wait_group 0;" ::: "memory");
    __syncthreads();

    // phase 0b: fold -0.5*sum(w) into biases (per map; warp w -> map w)
    {
        float s1 = (lane < 49) ? wsm[lane * 12 + wid] : 0.f;
        const int p2 = lane + 32;
        if (p2 < 49) s1 += wsm[p2 * 12 + wid];
        #pragma unroll
        for (int sft = 16; sft; sft >>= 1)
            s1 += __shfl_down_sync(0xffffffffu, s1, sft);
        if (lane == 0) wsm[OFF_SB2 + wid] -= 0.5f * s1;
    }
    __syncthreads();

    // phase 1: conv — positions pos0=tid, pos1=min(tid+352,560)
    const int pos0 = tid;
    const int pos1 = min(tid + 352, 560);
    const int r0 = pos0 / 33, c0 = pos0 - r0 * 33;
    const int r1 = pos1 / 33, c1 = pos1 - r1 * 33;
    const float* tp0 = sbuf + (r0 * 4) * TSTRIDE + c0 * 4;
    const float* tp1 = sbuf + (r1 * 4) * TSTRIDE + c1 * 4;

    unsigned long long acc2[2][6];
    {
        const ulonglong2 b01 =
            *reinterpret_cast<const ulonglong2*>(&wsm[OFF_SB2]);
        const ulonglong2 b23 =
            *reinterpret_cast<const ulonglong2*>(&wsm[OFF_SB2 + 4]);
        const ulonglong2 b45 =
            *reinterpret_cast<const ulonglong2*>(&wsm[OFF_SB2 + 8]);
        acc2[0][0] = b01.x; acc2[0][1] = b01.y;
        acc2[0][2] = b23.x; acc2[0][3] = b23.y;
        acc2[0][4] = b45.x; acc2[0][5] = b45.y;
        #pragma unroll
        for (int j = 0; j < 6; ++j) acc2[1][j] = acc2[0][j];
    }

    #pragma unroll
    for (int kh = 0; kh < 7; ++kh) {
        const float* rp0 = tp0 + kh * TSTRIDE;
        const float* rp1 = tp1 + kh * TSTRIDE;
        float4 Qa0 = *reinterpret_cast<const float4*>(rp0);
        float4 Qb0 = *reinterpret_cast<const float4*>(rp0 + 4);
        float4 Qa1 = *reinterpret_cast<const float4*>(rp1);
        float4 Qb1 = *reinterpret_cast<const float4*>(rp1 + 4);
        float v0[7] = {Qa0.y, Qa0.z, Qa0.w, Qb0.x, Qb0.y, Qb0.z, Qb0.w};
        float v1[7] = {Qa1.y, Qa1.z, Qa1.w, Qb1.x, Qb1.y, Qb1.z, Qb1.w};
        #pragma unroll
        for (int kw = 0; kw < 7; ++kw) {
            const int tapo = (kh * 7 + kw) * 12;
            unsigned long long vv0, vv1;
            asm("mov.b64 %0, {%1, %1};" : "=l"(vv0) : "f"(v0[kw]));
            asm("mov.b64 %0, {%1, %1};" : "=l"(vv1) : "f"(v1[kw]));
            const ulonglong2 w01 =
                *reinterpret_cast<const ulonglong2*>(&wsm[OFF_SW2 + tapo]);
            const ulonglong2 w23 =
                *reinterpret_cast<const ulonglong2*>(&wsm[OFF_SW2 + tapo + 4]);
            const ulonglong2 w45 =
                *reinterpret_cast<const ulonglong2*>(&wsm[OFF_SW2 + tapo + 8]);
            asm("fma.rn.f32x2 %0, %1, %2, %3;"
                : "=l"(acc2[0][0]) : "l"(w01.x), "l"(vv0), "l"(acc2[0][0]));
            asm("fma.rn.f32x2 %0, %1, %2, %3;"
                : "=l"(acc2[1][0]) : "l"(w01.x), "l"(vv1), "l"(acc2[1][0]));
            asm("fma.rn.f32x2 %0, %1, %2, %3;"
                : "=l"(acc2[0][1]) : "l"(w01.y), "l"(vv0), "l"(acc2[0][1]));
            asm("fma.rn.f32x2 %0, %1, %2, %3;"
                : "=l"(acc2[1][1]) : "l"(w01.y), "l"(vv1), "l"(acc2[1][1]));
            asm("fma.rn.f32x2 %0, %1, %2, %3;"
                : "=l"(acc2[0][2]) : "l"(w23.x), "l"(vv0), "l"(acc2[0][2]));
            asm("fma.rn.f32x2 %0, %1, %2, %3;"
                : "=l"(acc2[1][2]) : "l"(w23.x), "l"(vv1), "l"(acc2[1][2]));
            asm("fma.rn.f32x2 %0, %1, %2, %3;"
                : "=l"(acc2[0][3]) : "l"(w23.y), "l"(vv0), "l"(acc2[0][3]));
            asm("fma.rn.f32x2 %0, %1, %2, %3;"
                : "=l"(acc2[1][3]) : "l"(w23.y), "l"(vv1), "l"(acc2[1][3]));
            asm("fma.rn.f32x2 %0, %1, %2, %3;"
                : "=l"(acc2[0][4]) : "l"(w45.x), "l"(vv0), "l"(acc2[0][4]));
            asm("fma.rn.f32x2 %0, %1, %2, %3;"
                : "=l"(acc2[1][4]) : "l"(w45.x), "l"(vv1), "l"(acc2[1][4]));
            asm("fma.rn.f32x2 %0, %1, %2, %3;"
                : "=l"(acc2[0][5]) : "l"(w45.y), "l"(vv0), "l"(acc2[0][5]));
            asm("fma.rn.f32x2 %0, %1, %2, %3;"
                : "=l"(acc2[1][5]) : "l"(w45.y), "l"(vv1), "l"(acc2[1][5]));
        }
    }
    __syncthreads();                            // all tile reads done

    // phase 2: overlay scores into sbuf: s[k*561 + pos]
    #pragma unroll
    for (int j = 0; j < 6; ++j) {
        unsigned int lo0 = (unsigned int)(acc2[0][j] & 0xFFFFFFFFull);
        sbuf[(2 * j) * 561 + pos0] = __uint_as_float(lo0);
        if (j < 5) {
            unsigned int hi0 = (unsigned int)(acc2[0][j] >> 32);
            sbuf[(2 * j + 1) * 561 + pos0] = __uint_as_float(hi0);
        }
    }
    if (tid < 209) {
        #pragma unroll
        for (int j = 0; j < 6; ++j) {
            unsigned int lo1 = (unsigned int)(acc2[1][j] & 0xFFFFFFFFull);
            sbuf[(2 * j) * 561 + pos1] = __uint_as_float(lo1);
            if (j < 5) {
                unsigned int hi1 = (unsigned int)(acc2[1][j] >> 32);
                sbuf[(2 * j + 1) * 561 + pos1] = __uint_as_float(hi1);
            }
        }
    }
    __syncthreads();

    // phase 3: scan — warp wid handles map k = wid; lane = cell column
    {
        const int k = wid;
        const int gx = gx0 + lane;
        const int c1l = min(gx + 1, 127) - gx0;
        const float* s = sbuf + k * 561;
        const float4 tx4 = tab[gx];

        float a  = s[lane];
        float bq = s[c1l];
        float best = -3.0e38f;
        int bidx = 0x7fffffff;

        #pragma unroll 4
        for (int r = 0; r < 16; ++r) {
            const int gy = gy0 + r;
            const int y1l = min(gy + 1, 127) - gy0;
            const float cc = s[y1l * 33 + lane];
            const float dd = s[y1l * 33 + c1l];
            const float4 ty4 = tab[gy];
            const float ca = cc - a, db = dd - bq;
            {   // y-lo endpoint row
                float rl = fmaf(ty4.x, ca, a);
                float rr = fmaf(ty4.x, db, bq);
                float dx = rr - rl;
                bool hx = dx > 0.f;
                float w  = hx ? tx4.y : tx4.x;
                int  oxs = __float_as_int(hx ? tx4.w : tx4.z);
                float v = fmaf(w, dx, rl);
                int idx = (__float_as_int(ty4.z) << 9) + oxs;
                if (v > best) { best = v; bidx = idx; }
            }
            {   // y-hi endpoint row
                float rl = fmaf(ty4.y, ca, a);
                float rr = fmaf(ty4.y, db, bq);
                float dx = rr - rl;
                bool hx = dx > 0.f;
                float w  = hx ? tx4.y : tx4.x;
                int  oxs = __float_as_int(hx ? tx4.w : tx4.z);
                float v = fmaf(w, dx, rl);
                int idx = (__float_as_int(ty4.w) << 9) + oxs;
                if (v > best) { best = v; bidx = idx; }
            }
            a = cc; bq = dd;
        }

        #pragma unroll
        for (int sft = 16; sft; sft >>= 1) {
            float v2 = __shfl_down_sync(0xffffffffu, best, sft);
            int   i2 = __shfl_down_sync(0xffffffffu, bidx, sft);
            if (v2 > best || (v2 == best && i2 < bidx)) { best = v2; bidx = i2; }
        }
        if (lane == 0) {
            unsigned int u = __float_as_uint(best);
            u = (u & 0x80000000u) ? ~u : (u | 0x80000000u);
            unsigned long long key =
                ((unsigned long long)u << 32) | (0xFFFFFFFFu - (unsigned int)bidx);
            atomicMax(&g_best[b * NP + k], key);
        }
    }

    __syncthreads();
    if (tid == 0) {
        __threadfence();
        s_ticket = atomicAdd(&g_count[b], 1u);
    }
    __syncthreads();

    // phase 4: last block of this batch: cascades, warp k -> point k
    // (raw gather, pad 0.5; shift = p - 0.5*sum(cw) + cb; cw/cb from smem)
    if (s_ticket == 31u) {
        __threadfence();
        const int k = wid;
        unsigned long long key = 0ULL;
        if (lane == 0) key = atomicAdd(&g_best[b * NP + k], 0ULL);
        unsigned int lo =
            __shfl_sync(0xffffffffu, (unsigned int)(key & 0xFFFFFFFFull), 0);
        int idx = (int)(0xFFFFFFFFu - lo);
        float cx = (float)(idx & 511);
        float cy = (float)(idx >> 9);

        for (int casc = 0; casc < 3; ++casc) {
            int wi = (int)rintf(cx * 0.25f); wi = max(0, min(wi, 127));
            int hi = (int)rintf(cy * 0.25f); hi = max(0, min(hi, 127));
            float p0 = 0.f, p1 = 0.f, w0 = 0.f, w1 = 0.f;
            for (int t = lane; t < 49; t += 32) {
                int kh = t / 7, kw = t - kh * 7;
                int iy = hi * 4 - 3 + kh;
                int ix = wi * 4 - 3 + kw;
                float v = 0.5f;
                if (iy >= 0 && iy < IMH && ix >= 0 && ix < IMW)
                    v = imb[iy * IMW + ix];
                float c0v = wsm[OFF_CW + (casc * 2 + 0) * 49 + t];
                float c1v = wsm[OFF_CW + (casc * 2 + 1) * 49 + t];
                p0 += v * c0v;  w0 += c0v;
                p1 += v * c1v;  w1 += c1v;
            }
            #pragma unroll
            for (int sft = 16; sft; sft >>= 1) {
                p0 += __shfl_down_sync(0xffffffffu, p0, sft);
                p1 += __shfl_down_sync(0xffffffffu, p1, sft);
                w0 += __shfl_down_sync(0xffffffffu, w0, sft);
                w1 += __shfl_down_sync(0xffffffffu, w1, sft);
            }
            p0 = __shfl_sync(0xffffffffu, p0, 0);
            p1 = __shfl_sync(0xffffffffu, p1, 0);
            w0 = __shfl_sync(0xffffffffu, w0, 0);
            w1 = __shfl_sync(0xffffffffu, w1, 0);
            cx = cx + (p0 - 0.5f * w0) + wsm[OFF_CB + casc * 2 + 0];
            cy = cy + (p1 - 0.5f * w1) + wsm[OFF_CB + casc * 2 + 1];
        }
        if (lane == 0) {
            out[(b * NP + k) * 2 + 0] = cx;
            out[(b * NP + k) * 2 + 1] = cy;
        }
    }
}

// ---------------------------------------------------------------------------
extern "C" void kernel_launch(void* const* d_in, const int* in_sizes, int n_in,
                              void* d_out, int out_size) {
    const float* img = (const float*)d_in[0];
    const float* bw  = (const float*)d_in[1];
    const float* bb  = (const float*)d_in[2];
    const float* fcw = (const float*)d_in[3];
    const float* fcb = (const float*)d_in[4];
    const float* hw  = (const float*)d_in[5];
    const float* hb  = (const float*)d_in[6];
    float* out = (float*)d_out;

    prep_kernel<<<107, 256>>>(bw, bb, fcw, fcb, hw, hb);

    dim3 g(4, 8, BATCH);
    conv_scan_kernel<<<g, 352>>>(img, out);
}